// round 15
// baseline (speedup 1.0000x reference)
#include <cuda_runtime.h>
#include <cuda_bf16.h>
#include <stdint.h>

#define BATCH 512
#define DIM   256
#define QUEUE 65536
#define NROWS 1024
#define NSB   1024          // 64-row queue sub-blocks
#define QG    8             // queue tiles (128 rows) per screen CTA
#define MARGIN 0.05f

// ---------------- device scratch (allocations forbidden) ----------------
__device__ __align__(16) float          g_P [NROWS * DIM];   // normalized fp32
__device__ __align__(16) __nv_bfloat16  g_Pb[NROWS * DIM];   // normalized bf16
__device__ __align__(16) __nv_bfloat16  g_Qb[QUEUE * DIM];   // queue bf16
__device__ unsigned                     g_tmU[NROWS * NSB];  // ordered-float keys of subblock maxima
__device__ unsigned long long           g_best[NROWS];       // packed (key<<32 | ~idx), exact
__device__ __align__(16) float          g_S[2 * BATCH * BATCH];

// ---------------- helpers ----------------
__device__ __forceinline__ unsigned float_key(float v) {
    unsigned u = __float_as_uint(v);
    return (u & 0x80000000u) ? ~u : (u | 0x80000000u);
}
__device__ __forceinline__ float key_float(unsigned k) {
    unsigned u = (k & 0x80000000u) ? (k & 0x7FFFFFFFu) : ~k;
    return __uint_as_float(u);
}
__device__ __forceinline__ uint32_t smem_u32(const void* p) {
    uint32_t a;
    asm("{ .reg .u64 t; cvta.to.shared.u64 t, %1; cvt.u32.u64 %0, t; }" : "=r"(a) : "l"(p));
    return a;
}
__device__ __forceinline__ void ldsm_x4(uint32_t& r0, uint32_t& r1, uint32_t& r2, uint32_t& r3,
                                        uint32_t addr) {
    asm volatile("ldmatrix.sync.aligned.m8n8.x4.shared.b16 {%0,%1,%2,%3}, [%4];"
                 : "=r"(r0), "=r"(r1), "=r"(r2), "=r"(r3) : "r"(addr));
}
__device__ __forceinline__ void mma16816(float* c, const uint32_t* a, const uint32_t* b) {
    asm volatile(
        "mma.sync.aligned.m16n8k16.row.col.f32.bf16.bf16.f32 "
        "{%0,%1,%2,%3}, {%4,%5,%6,%7}, {%8,%9}, {%0,%1,%2,%3};"
        : "+f"(c[0]), "+f"(c[1]), "+f"(c[2]), "+f"(c[3])
        : "r"(a[0]), "r"(a[1]), "r"(a[2]), "r"(a[3]), "r"(b[0]), "r"(b[1]));
}

// ---------------- kernel 0: queue shift + bf16 convert (fused) ----------------
__global__ void __launch_bounds__(256) shiftconv_kernel(const float* __restrict__ fq,
                                                        float* __restrict__ out) {
    size_t i = ((size_t)blockIdx.x * 256 + threadIdx.x) * 4;
    float4 v = *(const float4*)(fq + i);
    *(__nv_bfloat162*)(g_Qb + i)     = __floats2bfloat162_rn(v.x, v.y);
    *(__nv_bfloat162*)(g_Qb + i + 2) = __floats2bfloat162_rn(v.z, v.w);
    size_t row = i >> 8;
    if (row < (size_t)(QUEUE - BATCH))
        *(float4*)(out + 2048 + (row + BATCH) * DIM + (i & 255)) = v;
}

// ---------------- kernel 1: L2 normalize ----------------
__global__ void __launch_bounds__(256) norm_kernel(const float* __restrict__ p1,
                                                   const float* __restrict__ p2,
                                                   float* __restrict__ outq) {
    int row = blockIdx.x, t = threadIdx.x;
    const float* src = (row < BATCH) ? (p1 + (size_t)row * DIM)
                                     : (p2 + (size_t)(row - BATCH) * DIM);
    float x = src[t];
    float s = x * x;
    #pragma unroll
    for (int off = 16; off; off >>= 1) s += __shfl_xor_sync(0xFFFFFFFFu, s, off);
    __shared__ float ws[8];
    if ((t & 31) == 0) ws[t >> 5] = s;
    __syncthreads();
    float sum = 0.f;
    #pragma unroll
    for (int i = 0; i < 8; i++) sum += ws[i];
    float sc = rsqrtf(fmaxf(sum, 1e-12f));
    float y = x * sc;
    g_P[row * DIM + t]  = y;
    g_Pb[row * DIM + t] = __float2bfloat16(y);
    if (row < BATCH) outq[(size_t)row * DIM + t] = y;
}

// ---------------- kernel 2: bf16 mma.sync screen ----------------
// grid (64, 8): bx = group of 8 queue tiles (128 rows each), by = 128-row P group.
// smem layout (chunked k-major): byte = kc*4096 + row*32 + half*16, XOR'd by ((row&4)<<2).
// A at [0, 64K), B at [64K, 128K).
__global__ void __launch_bounds__(256) screen_kernel() {
    extern __shared__ __align__(16) char smem[];
    const uint32_t sbase = smem_u32(smem);
    const int tid = threadIdx.x;
    const int lane = tid & 31, w = tid >> 5;
    const int wm = w >> 2, wn = w & 3;           // warp 64(M) x 32(N) tile
    const int qg = blockIdx.x, pg = blockIdx.y;

    // ---- load A (P group: 128 rows x 256 bf16) ----
    #pragma unroll
    for (int i = 0; i < 16; i++) {
        int idx = i * 256 + tid;                 // 16B chunk id
        int row = idx >> 5, ch = idx & 31;       // 32 chunks of 8 bf16 per row
        uint4 v = *(const uint4*)&g_Pb[(size_t)(pg * 128 + row) * DIM + ch * 8];
        uint32_t off = (uint32_t)((ch >> 1) * 4096 + row * 32 + (ch & 1) * 16);
        off ^= (row & 4) << 2;
        *(uint4*)(smem + off) = v;
    }

    // per-lane ldmatrix address constants
    uint32_t a_addr[4], b_addr[2];
    #pragma unroll
    for (int mi = 0; mi < 4; mi++) {
        uint32_t off = (uint32_t)((wm * 64 + mi * 16 + (lane & 15)) * 32 + (lane >> 4) * 16);
        off ^= (lane & 4) << 2;
        a_addr[mi] = sbase + off;
    }
    #pragma unroll
    for (int ni2 = 0; ni2 < 2; ni2++) {
        uint32_t off = (uint32_t)((wn * 32 + ni2 * 16 + (lane & 15)) * 32 + (lane >> 4) * 16);
        off ^= (lane & 4) << 2;
        b_addr[ni2] = sbase + 65536 + off;
    }

    for (int t8 = 0; t8 < QG; t8++) {
        const int qt = qg * QG + t8;
        // ---- load B (queue tile: 128 rows x 256 bf16) ----
        #pragma unroll
        for (int i = 0; i < 16; i++) {
            int idx = i * 256 + tid;
            int row = idx >> 5, ch = idx & 31;
            uint4 v = *(const uint4*)&g_Qb[((size_t)qt * 128 + row) * DIM + ch * 8];
            uint32_t off = (uint32_t)((ch >> 1) * 4096 + row * 32 + (ch & 1) * 16);
            off ^= (row & 4) << 2;
            *(uint4*)(smem + 65536 + off) = v;
        }
        __syncthreads();

        float c[4][4][4];
        #pragma unroll
        for (int mi = 0; mi < 4; mi++)
            #pragma unroll
            for (int ni = 0; ni < 4; ni++)
                #pragma unroll
                for (int e = 0; e < 4; e++) c[mi][ni][e] = 0.f;

        #pragma unroll
        for (int ks = 0; ks < 16; ks++) {
            const uint32_t kb = (uint32_t)(ks * 4096);
            uint32_t a[4][4];
            #pragma unroll
            for (int mi = 0; mi < 4; mi++)
                ldsm_x4(a[mi][0], a[mi][1], a[mi][2], a[mi][3], a_addr[mi] + kb);
            uint32_t b[4][2];
            #pragma unroll
            for (int ni2 = 0; ni2 < 2; ni2++) {
                uint32_t r0, r1, r2, r3;
                ldsm_x4(r0, r1, r2, r3, b_addr[ni2] + kb);
                b[ni2 * 2 + 0][0] = r0; b[ni2 * 2 + 0][1] = r2;   // n 0..7  (k-lo, k-hi)
                b[ni2 * 2 + 1][0] = r1; b[ni2 * 2 + 1][1] = r3;   // n 8..15
            }
            #pragma unroll
            for (int mi = 0; mi < 4; mi++)
                #pragma unroll
                for (int ni = 0; ni < 4; ni++)
                    mma16816(c[mi][ni], a[mi], b[ni]);
        }

        // ---- epilogue: per (row, 64-subblock) max ----
        const int sb = qt * 2 + (wn >> 1);       // warp's 32 cols lie in one 64-subblock
        #pragma unroll
        for (int mi = 0; mi < 4; mi++) {
            float mlo = -1e30f, mhi = -1e30f;
            #pragma unroll
            for (int ni = 0; ni < 4; ni++) {
                mlo = fmaxf(mlo, fmaxf(c[mi][ni][0], c[mi][ni][1]));
                mhi = fmaxf(mhi, fmaxf(c[mi][ni][2], c[mi][ni][3]));
            }
            #pragma unroll
            for (int off = 1; off <= 2; off <<= 1) {
                mlo = fmaxf(mlo, __shfl_xor_sync(0xFFFFFFFFu, mlo, off));
                mhi = fmaxf(mhi, __shfl_xor_sync(0xFFFFFFFFu, mhi, off));
            }
            if ((lane & 3) == 0) {
                int rlo = pg * 128 + wm * 64 + mi * 16 + (lane >> 2);
                atomicMax(&g_tmU[(size_t)rlo * NSB + sb], float_key(mlo));
                atomicMax(&g_tmU[(size_t)(rlo + 8) * NSB + sb], float_key(mhi));
            }
        }
        __syncthreads();
    }
}

// ---------------- kernel 3: exact fp32 recheck ----------------
// one block (256 thr) per P row; 4 threads per candidate queue row.
__global__ void __launch_bounds__(256) recheck_kernel(const float* __restrict__ fq) {
    const int row = blockIdx.x, t = threadIdx.x, wid = t >> 5, lid = t & 31;
    __shared__ __align__(16) float Pk[DIM];
    __shared__ unsigned tmk[NSB];
    __shared__ unsigned redk[8];
    __shared__ unsigned long long redb[8];

    Pk[t] = g_P[row * DIM + t];
    unsigned mk = 0;
    #pragma unroll
    for (int i = 0; i < 4; i++) {
        unsigned k = g_tmU[(size_t)row * NSB + t + i * 256];
        tmk[t + i * 256] = k;
        mk = max(mk, k);
    }
    #pragma unroll
    for (int off = 16; off; off >>= 1) mk = max(mk, __shfl_xor_sync(0xFFFFFFFFu, mk, off));
    if (lid == 0) redk[wid] = mk;
    __syncthreads();
    unsigned maxk = 0;
    #pragma unroll
    for (int w = 0; w < 8; w++) maxk = max(maxk, redk[w]);
    const float thr = key_float(maxk) - MARGIN;

    unsigned long long best = 0ULL;
    const int qsub = t >> 2, quarter = t & 3;    // 64 q rows x 4 k-quarters
    for (int sb = 0; sb < NSB; sb++) {
        if (key_float(tmk[sb]) < thr) continue;
        unsigned q = (unsigned)(sb * 64 + qsub);
        const float4* qr = (const float4*)(fq + (size_t)q * DIM + quarter * 64);
        const float4* pr = (const float4*)(Pk + quarter * 64);
        float s = 0.f;
        #pragma unroll
        for (int k = 0; k < 16; k++) {
            float4 v = qr[k], p = pr[k];
            s += v.x * p.x + v.y * p.y + v.z * p.z + v.w * p.w;
        }
        s += __shfl_xor_sync(0xFFFFFFFFu, s, 1);
        s += __shfl_xor_sync(0xFFFFFFFFu, s, 2);
        if (quarter == 0) {
            unsigned long long pk = ((unsigned long long)float_key(s) << 32) | (unsigned)(~q);
            best = (pk > best) ? pk : best;
        }
    }
    #pragma unroll
    for (int off = 16; off; off >>= 1) {
        unsigned long long o = __shfl_xor_sync(0xFFFFFFFFu, best, off);
        best = (o > best) ? o : best;
    }
    if (lid == 0) redb[wid] = best;
    __syncthreads();
    if (t == 0) {
        unsigned long long m = redb[0];
        #pragma unroll
        for (int w = 1; w < 8; w++) m = (redb[w] > m) ? redb[w] : m;
        g_best[row] = m;
    }
}

// ---------------- kernel 4: logits S_z = NN_z . P_other^T / T ----------------
__global__ void __launch_bounds__(256) logits_kernel(const float* __restrict__ fq) {
    __shared__ float As[64][34];
    __shared__ float Bs[64][34];
    const int tx = threadIdx.x, ty = threadIdx.y;
    const int t = ty * 16 + tx;
    const int bx = blockIdx.x, by = blockIdx.y, z = blockIdx.z;
    const int zoff = z ? 0 : BATCH;

    float acc[4][4];
    #pragma unroll
    for (int i = 0; i < 4; i++)
        #pragma unroll
        for (int j = 0; j < 4; j++) acc[i][j] = 0.f;

    for (int kc = 0; kc < DIM; kc += 32) {
        __syncthreads();
        #pragma unroll
        for (int l = 0; l < 2; ++l) {
            int idx = l * 256 + t;
            int row = idx >> 3;
            int k4  = (idx & 7) * 4;
            unsigned q = ~(unsigned)(g_best[z * BATCH + by * 64 + row] & 0xFFFFFFFFu);
            float4 v = *(const float4*)&fq[(size_t)q * DIM + kc + k4];
            As[row][k4 + 0] = v.x; As[row][k4 + 1] = v.y;
            As[row][k4 + 2] = v.z; As[row][k4 + 3] = v.w;
            float4 w = *(const float4*)&g_P[(size_t)(zoff + bx * 64 + row) * DIM + kc + k4];
            Bs[row][k4 + 0] = w.x; Bs[row][k4 + 1] = w.y;
            Bs[row][k4 + 2] = w.z; Bs[row][k4 + 3] = w.w;
        }
        __syncthreads();
        #pragma unroll
        for (int k = 0; k < 32; k++) {
            float a[4], b[4];
            #pragma unroll
            for (int i = 0; i < 4; i++) a[i] = As[ty * 4 + i][k];
            #pragma unroll
            for (int j = 0; j < 4; j++) b[j] = Bs[tx + 16 * j][k];
            #pragma unroll
            for (int i = 0; i < 4; i++)
                #pragma unroll
                for (int j = 0; j < 4; j++) acc[i][j] = fmaf(a[i], b[j], acc[i][j]);
        }
    }
    #pragma unroll
    for (int i = 0; i < 4; i++) {
        int brow = by * 64 + ty * 4 + i;
        #pragma unroll
        for (int j = 0; j < 4; j++) {
            int ccol = bx * 64 + tx + 16 * j;
            g_S[((size_t)z * BATCH + brow) * BATCH + ccol] = acc[i][j] * 10.0f;
        }
    }
}

// ---------------- kernel 5: loss (row / column log-softmax) ----------------
__global__ void __launch_bounds__(512) loss_kernel(float* __restrict__ out) {
    const int r = blockIdx.x, t = threadIdx.x;
    const int g = r >> 9, i = r & 511;
    const int z = g >> 1, colside = g & 1;
    const float* S = g_S + (size_t)z * BATCH * BATCH;
    float v = colside ? S[(size_t)t * BATCH + i] : S[(size_t)i * BATCH + t];
    float diag = S[(size_t)i * BATCH + i];

    __shared__ float red[16];
    float m = v;
    #pragma unroll
    for (int off = 16; off; off >>= 1) m = fmaxf(m, __shfl_xor_sync(0xFFFFFFFFu, m, off));
    if ((t & 31) == 0) red[t >> 5] = m;
    __syncthreads();
    if (t == 0) {
        float mm = red[0];
        #pragma unroll
        for (int w = 1; w < 16; w++) mm = fmaxf(mm, red[w]);
        red[0] = mm;
    }
    __syncthreads();
    m = red[0];
    __syncthreads();

    float e = __expf(v - m);
    #pragma unroll
    for (int off = 16; off; off >>= 1) e += __shfl_xor_sync(0xFFFFFFFFu, e, off);
    if ((t & 31) == 0) red[t >> 5] = e;
    __syncthreads();
    if (t == 0) {
        float sum = 0.f;
        #pragma unroll
        for (int w = 0; w < 16; w++) sum += red[w];
        out[r] = m + logf(sum) - diag;
    }
}

// ---------------- launch ----------------
extern "C" void kernel_launch(void* const* d_in, const int* in_sizes, int n_in,
                              void* d_out, int out_size) {
    const float* p1 = (const float*)d_in[0];
    const float* p2 = (const float*)d_in[1];
    const float* fq = (const float*)d_in[2];
    float* out = (float*)d_out;

    static int init_done = 0;
    if (!init_done) {
        cudaFuncSetAttribute(screen_kernel, cudaFuncAttributeMaxDynamicSharedMemorySize,
                             131072);
        init_done = 1;
    }

    void* tm_ptr = nullptr;
    cudaGetSymbolAddress(&tm_ptr, g_tmU);
    cudaMemsetAsync(tm_ptr, 0, (size_t)NROWS * NSB * sizeof(unsigned), 0);

    shiftconv_kernel<<<QUEUE * DIM / (256 * 4), 256>>>(fq, out);
    norm_kernel<<<NROWS, 256>>>(p1, p2, out + 2048);
    screen_kernel<<<dim3(64, 8), 256, 131072>>>();
    recheck_kernel<<<NROWS, 256>>>(fq);
    logits_kernel<<<dim3(8, 8, 2), dim3(16, 16)>>>(fq);
    loss_kernel<<<2048, 512>>>(out);
}

// round 16
// speedup vs baseline: 4.5287x; 4.5287x over previous
#include <cuda_runtime.h>
#include <cuda_bf16.h>
#include <stdint.h>

#define BATCH 512
#define DIM   256
#define QUEUE 65536
#define NROWS 1024
#define NSB   1024          // 64-row queue sub-blocks
#define QG    8             // queue tiles (128 rows) per screen CTA
#define SB_MARGIN 0.016f
#define EL_MARGIN 0.012f
#define MAXCAND 256

// ---------------- device scratch (allocations forbidden) ----------------
__device__ __align__(16) float          g_P [NROWS * DIM];   // normalized fp32
__device__ __align__(16) __nv_bfloat16  g_Pb[NROWS * DIM];   // normalized bf16
__device__ __align__(16) __nv_bfloat16  g_Qb[QUEUE * DIM];   // queue bf16
__device__ __align__(16) __nv_bfloat16  g_sim[(size_t)NROWS * QUEUE]; // bf16 sims (128MB)
__device__ unsigned                     g_tmU[NROWS * NSB];  // ordered-float keys of subblock maxima
__device__ unsigned long long           g_best[NROWS];       // packed (key<<32 | ~idx), exact
__device__ __align__(16) float          g_S[2 * BATCH * BATCH];

// ---------------- helpers ----------------
__device__ __forceinline__ unsigned float_key(float v) {
    unsigned u = __float_as_uint(v);
    return (u & 0x80000000u) ? ~u : (u | 0x80000000u);
}
__device__ __forceinline__ float key_float(unsigned k) {
    unsigned u = (k & 0x80000000u) ? (k & 0x7FFFFFFFu) : ~k;
    return __uint_as_float(u);
}
__device__ __forceinline__ uint32_t smem_u32(const void* p) {
    uint32_t a;
    asm("{ .reg .u64 t; cvta.to.shared.u64 t, %1; cvt.u32.u64 %0, t; }" : "=r"(a) : "l"(p));
    return a;
}
__device__ __forceinline__ void ldsm_x4(uint32_t& r0, uint32_t& r1, uint32_t& r2, uint32_t& r3,
                                        uint32_t addr) {
    asm volatile("ldmatrix.sync.aligned.m8n8.x4.shared.b16 {%0,%1,%2,%3}, [%4];"
                 : "=r"(r0), "=r"(r1), "=r"(r2), "=r"(r3) : "r"(addr));
}
__device__ __forceinline__ void mma16816(float* c, const uint32_t* a, const uint32_t* b) {
    asm volatile(
        "mma.sync.aligned.m16n8k16.row.col.f32.bf16.bf16.f32 "
        "{%0,%1,%2,%3}, {%4,%5,%6,%7}, {%8,%9}, {%0,%1,%2,%3};"
        : "+f"(c[0]), "+f"(c[1]), "+f"(c[2]), "+f"(c[3])
        : "r"(a[0]), "r"(a[1]), "r"(a[2]), "r"(a[3]), "r"(b[0]), "r"(b[1]));
}

// ---------------- kernel 0: queue shift + bf16 convert (fused) ----------------
__global__ void __launch_bounds__(256) shiftconv_kernel(const float* __restrict__ fq,
                                                        float* __restrict__ out) {
    size_t i = ((size_t)blockIdx.x * 256 + threadIdx.x) * 4;
    float4 v = *(const float4*)(fq + i);
    *(__nv_bfloat162*)(g_Qb + i)     = __floats2bfloat162_rn(v.x, v.y);
    *(__nv_bfloat162*)(g_Qb + i + 2) = __floats2bfloat162_rn(v.z, v.w);
    size_t row = i >> 8;
    if (row < (size_t)(QUEUE - BATCH))
        *(float4*)(out + 2048 + (row + BATCH) * DIM + (i & 255)) = v;
}

// ---------------- kernel 1: L2 normalize ----------------
__global__ void __launch_bounds__(256) norm_kernel(const float* __restrict__ p1,
                                                   const float* __restrict__ p2,
                                                   float* __restrict__ outq) {
    int row = blockIdx.x, t = threadIdx.x;
    const float* src = (row < BATCH) ? (p1 + (size_t)row * DIM)
                                     : (p2 + (size_t)(row - BATCH) * DIM);
    float x = src[t];
    float s = x * x;
    #pragma unroll
    for (int off = 16; off; off >>= 1) s += __shfl_xor_sync(0xFFFFFFFFu, s, off);
    __shared__ float ws[8];
    if ((t & 31) == 0) ws[t >> 5] = s;
    __syncthreads();
    float sum = 0.f;
    #pragma unroll
    for (int i = 0; i < 8; i++) sum += ws[i];
    float sc = rsqrtf(fmaxf(sum, 1e-12f));
    float y = x * sc;
    g_P[row * DIM + t]  = y;
    g_Pb[row * DIM + t] = __float2bfloat16(y);
    if (row < BATCH) outq[(size_t)row * DIM + t] = y;
}

// ---------------- kernel 2: bf16 mma.sync screen ----------------
// grid (64, 8): bx = group of 8 queue tiles (128 rows each), by = 128-row P group.
// smem layout (chunked k-major): byte = kc*4096 + row*32 + half*16, XOR'd by ((row&4)<<2).
// A at [0, 64K), B at [64K, 128K).
__global__ void __launch_bounds__(256) screen_kernel() {
    extern __shared__ __align__(16) char smem[];
    const uint32_t sbase = smem_u32(smem);
    const int tid = threadIdx.x;
    const int lane = tid & 31, w = tid >> 5;
    const int wm = w >> 2, wn = w & 3;           // warp 64(M) x 32(N) tile
    const int qg = blockIdx.x, pg = blockIdx.y;

    // ---- load A (P group: 128 rows x 256 bf16) ----
    #pragma unroll
    for (int i = 0; i < 16; i++) {
        int idx = i * 256 + tid;                 // 16B chunk id
        int row = idx >> 5, ch = idx & 31;
        uint4 v = *(const uint4*)&g_Pb[(size_t)(pg * 128 + row) * DIM + ch * 8];
        uint32_t off = (uint32_t)((ch >> 1) * 4096 + row * 32 + (ch & 1) * 16);
        off ^= (row & 4) << 2;
        *(uint4*)(smem + off) = v;
    }

    // per-lane ldmatrix address constants
    uint32_t a_addr[4], b_addr[2];
    #pragma unroll
    for (int mi = 0; mi < 4; mi++) {
        uint32_t off = (uint32_t)((wm * 64 + mi * 16 + (lane & 15)) * 32 + (lane >> 4) * 16);
        off ^= (lane & 4) << 2;
        a_addr[mi] = sbase + off;
    }
    #pragma unroll
    for (int ni2 = 0; ni2 < 2; ni2++) {
        uint32_t off = (uint32_t)((wn * 32 + ni2 * 16 + (lane & 15)) * 32 + (lane >> 4) * 16);
        off ^= (lane & 4) << 2;
        b_addr[ni2] = sbase + 65536 + off;
    }

    for (int t8 = 0; t8 < QG; t8++) {
        const int qt = qg * QG + t8;
        // ---- load B (queue tile: 128 rows x 256 bf16) ----
        #pragma unroll
        for (int i = 0; i < 16; i++) {
            int idx = i * 256 + tid;
            int row = idx >> 5, ch = idx & 31;
            uint4 v = *(const uint4*)&g_Qb[((size_t)qt * 128 + row) * DIM + ch * 8];
            uint32_t off = (uint32_t)((ch >> 1) * 4096 + row * 32 + (ch & 1) * 16);
            off ^= (row & 4) << 2;
            *(uint4*)(smem + 65536 + off) = v;
        }
        __syncthreads();

        float c[4][4][4];
        #pragma unroll
        for (int mi = 0; mi < 4; mi++)
            #pragma unroll
            for (int ni = 0; ni < 4; ni++)
                #pragma unroll
                for (int e = 0; e < 4; e++) c[mi][ni][e] = 0.f;

        #pragma unroll
        for (int ks = 0; ks < 16; ks++) {
            const uint32_t kb = (uint32_t)(ks * 4096);
            uint32_t a[4][4];
            #pragma unroll
            for (int mi = 0; mi < 4; mi++)
                ldsm_x4(a[mi][0], a[mi][1], a[mi][2], a[mi][3], a_addr[mi] + kb);
            uint32_t b[4][2];
            #pragma unroll
            for (int ni2 = 0; ni2 < 2; ni2++) {
                uint32_t r0, r1, r2, r3;
                ldsm_x4(r0, r1, r2, r3, b_addr[ni2] + kb);
                b[ni2 * 2 + 0][0] = r0; b[ni2 * 2 + 0][1] = r2;
                b[ni2 * 2 + 1][0] = r1; b[ni2 * 2 + 1][1] = r3;
            }
            #pragma unroll
            for (int mi = 0; mi < 4; mi++)
                #pragma unroll
                for (int ni = 0; ni < 4; ni++)
                    mma16816(c[mi][ni], a[mi], b[ni]);
        }

        // ---- epilogue: store bf16 sims + per (row, 64-subblock) max ----
        const int sb = qt * 2 + (wn >> 1);
        #pragma unroll
        for (int mi = 0; mi < 4; mi++) {
            const int rlo = pg * 128 + wm * 64 + mi * 16 + (lane >> 2);
            float mlo = -1e30f, mhi = -1e30f;
            #pragma unroll
            for (int ni = 0; ni < 4; ni++) {
                const int col = qt * 128 + wn * 32 + ni * 8 + (lane & 3) * 2;
                *(__nv_bfloat162*)&g_sim[(size_t)rlo * QUEUE + col] =
                    __floats2bfloat162_rn(c[mi][ni][0], c[mi][ni][1]);
                *(__nv_bfloat162*)&g_sim[(size_t)(rlo + 8) * QUEUE + col] =
                    __floats2bfloat162_rn(c[mi][ni][2], c[mi][ni][3]);
                mlo = fmaxf(mlo, fmaxf(c[mi][ni][0], c[mi][ni][1]));
                mhi = fmaxf(mhi, fmaxf(c[mi][ni][2], c[mi][ni][3]));
            }
            #pragma unroll
            for (int off = 1; off <= 2; off <<= 1) {
                mlo = fmaxf(mlo, __shfl_xor_sync(0xFFFFFFFFu, mlo, off));
                mhi = fmaxf(mhi, __shfl_xor_sync(0xFFFFFFFFu, mhi, off));
            }
            if ((lane & 3) == 0) {
                atomicMax(&g_tmU[(size_t)rlo * NSB + sb], float_key(mlo));
                atomicMax(&g_tmU[(size_t)(rlo + 8) * NSB + sb], float_key(mhi));
            }
        }
        __syncthreads();
    }
}

// ---------------- kernel 3: element-granularity exact recheck ----------------
// one block (256 thr) per P row.
__global__ void __launch_bounds__(256) recheck_kernel(const float* __restrict__ fq) {
    const int row = blockIdx.x, t = threadIdx.x, wid = t >> 5, lane = t & 31;
    __shared__ __align__(16) float Pk[DIM];
    __shared__ unsigned redk[8];
    __shared__ int cand[MAXCAND];
    __shared__ int ccount;
    __shared__ unsigned long long cbest[MAXCAND];

    if (t == 0) ccount = 0;
    Pk[t] = g_P[row * DIM + t];

    unsigned myk[4];
    unsigned mk = 0;
    #pragma unroll
    for (int i = 0; i < 4; i++) {
        myk[i] = g_tmU[(size_t)row * NSB + t + i * 256];
        mk = max(mk, myk[i]);
    }
    #pragma unroll
    for (int off = 16; off; off >>= 1) mk = max(mk, __shfl_xor_sync(0xFFFFFFFFu, mk, off));
    if (lane == 0) redk[wid] = mk;
    __syncthreads();
    unsigned maxk = 0;
    #pragma unroll
    for (int w2 = 0; w2 < 8; w2++) maxk = max(maxk, redk[w2]);
    const float fmaxv  = key_float(maxk);
    const float sb_thr = fmaxv - SB_MARGIN;
    const float el_thr = fmaxv - EL_MARGIN;

    // phase A: candidate discovery from stored bf16 sims
    #pragma unroll
    for (int i = 0; i < 4; i++) {
        int sb = t + i * 256;
        if (key_float(myk[i]) >= sb_thr) {
            const __nv_bfloat162* sp =
                (const __nv_bfloat162*)&g_sim[(size_t)row * QUEUE + sb * 64];
            #pragma unroll 4
            for (int j = 0; j < 32; j++) {
                __nv_bfloat162 v = sp[j];
                float lo = __bfloat162float(v.x);
                float hi = __bfloat162float(v.y);
                if (lo >= el_thr) {
                    int ix = atomicAdd(&ccount, 1);
                    if (ix < MAXCAND) cand[ix] = sb * 64 + j * 2;
                }
                if (hi >= el_thr) {
                    int ix = atomicAdd(&ccount, 1);
                    if (ix < MAXCAND) cand[ix] = sb * 64 + j * 2 + 1;
                }
            }
        }
    }
    __syncthreads();
    const int C = min(ccount, MAXCAND);

    // phase B: exact fp32 dot per candidate, one warp each
    for (int ci = wid; ci < C; ci += 8) {
        unsigned q = (unsigned)cand[ci];
        const float* qr = fq + (size_t)q * DIM;
        float s = 0.f;
        #pragma unroll
        for (int k = 0; k < 8; k++)
            s = fmaf(qr[lane + 32 * k], Pk[lane + 32 * k], s);
        #pragma unroll
        for (int off = 16; off; off >>= 1) s += __shfl_xor_sync(0xFFFFFFFFu, s, off);
        if (lane == 0)
            cbest[ci] = ((unsigned long long)float_key(s) << 32) | (unsigned)(~q);
    }
    __syncthreads();
    if (t == 0) {
        unsigned long long m = 0ULL;
        for (int ci = 0; ci < C; ci++) m = (cbest[ci] > m) ? cbest[ci] : m;
        g_best[row] = m;
    }
}

// ---------------- kernel 4: logits S_z = NN_z . P_other^T / T ----------------
__global__ void __launch_bounds__(256) logits_kernel(const float* __restrict__ fq) {
    __shared__ float As[64][34];
    __shared__ float Bs[64][34];
    const int tx = threadIdx.x, ty = threadIdx.y;
    const int t = ty * 16 + tx;
    const int bx = blockIdx.x, by = blockIdx.y, z = blockIdx.z;
    const int zoff = z ? 0 : BATCH;

    float acc[4][4];
    #pragma unroll
    for (int i = 0; i < 4; i++)
        #pragma unroll
        for (int j = 0; j < 4; j++) acc[i][j] = 0.f;

    for (int kc = 0; kc < DIM; kc += 32) {
        __syncthreads();
        #pragma unroll
        for (int l = 0; l < 2; ++l) {
            int idx = l * 256 + t;
            int row = idx >> 3;
            int k4  = (idx & 7) * 4;
            unsigned q = ~(unsigned)(g_best[z * BATCH + by * 64 + row] & 0xFFFFFFFFu);
            float4 v = *(const float4*)&fq[(size_t)q * DIM + kc + k4];
            As[row][k4 + 0] = v.x; As[row][k4 + 1] = v.y;
            As[row][k4 + 2] = v.z; As[row][k4 + 3] = v.w;
            float4 w = *(const float4*)&g_P[(size_t)(zoff + bx * 64 + row) * DIM + kc + k4];
            Bs[row][k4 + 0] = w.x; Bs[row][k4 + 1] = w.y;
            Bs[row][k4 + 2] = w.z; Bs[row][k4 + 3] = w.w;
        }
        __syncthreads();
        #pragma unroll
        for (int k = 0; k < 32; k++) {
            float a[4], b[4];
            #pragma unroll
            for (int i = 0; i < 4; i++) a[i] = As[ty * 4 + i][k];
            #pragma unroll
            for (int j = 0; j < 4; j++) b[j] = Bs[tx + 16 * j][k];
            #pragma unroll
            for (int i = 0; i < 4; i++)
                #pragma unroll
                for (int j = 0; j < 4; j++) acc[i][j] = fmaf(a[i], b[j], acc[i][j]);
        }
    }
    #pragma unroll
    for (int i = 0; i < 4; i++) {
        int brow = by * 64 + ty * 4 + i;
        #pragma unroll
        for (int j = 0; j < 4; j++) {
            int ccol = bx * 64 + tx + 16 * j;
            g_S[((size_t)z * BATCH + brow) * BATCH + ccol] = acc[i][j] * 10.0f;
        }
    }
}

// ---------------- kernel 5: loss (row / column log-softmax) ----------------
__global__ void __launch_bounds__(512) loss_kernel(float* __restrict__ out) {
    const int r = blockIdx.x, t = threadIdx.x;
    const int g = r >> 9, i = r & 511;
    const int z = g >> 1, colside = g & 1;
    const float* S = g_S + (size_t)z * BATCH * BATCH;
    float v = colside ? S[(size_t)t * BATCH + i] : S[(size_t)i * BATCH + t];
    float diag = S[(size_t)i * BATCH + i];

    __shared__ float red[16];
    float m = v;
    #pragma unroll
    for (int off = 16; off; off >>= 1) m = fmaxf(m, __shfl_xor_sync(0xFFFFFFFFu, m, off));
    if ((t & 31) == 0) red[t >> 5] = m;
    __syncthreads();
    if (t == 0) {
        float mm = red[0];
        #pragma unroll
        for (int w = 1; w < 16; w++) mm = fmaxf(mm, red[w]);
        red[0] = mm;
    }
    __syncthreads();
    m = red[0];
    __syncthreads();

    float e = __expf(v - m);
    #pragma unroll
    for (int off = 16; off; off >>= 1) e += __shfl_xor_sync(0xFFFFFFFFu, e, off);
    if ((t & 31) == 0) red[t >> 5] = e;
    __syncthreads();
    if (t == 0) {
        float sum = 0.f;
        #pragma unroll
        for (int w = 0; w < 16; w++) sum += red[w];
        out[r] = m + logf(sum) - diag;
    }
}

// ---------------- launch ----------------
extern "C" void kernel_launch(void* const* d_in, const int* in_sizes, int n_in,
                              void* d_out, int out_size) {
    const float* p1 = (const float*)d_in[0];
    const float* p2 = (const float*)d_in[1];
    const float* fq = (const float*)d_in[2];
    float* out = (float*)d_out;

    static int init_done = 0;
    if (!init_done) {
        cudaFuncSetAttribute(screen_kernel, cudaFuncAttributeMaxDynamicSharedMemorySize,
                             131072);
        init_done = 1;
    }

    void* tm_ptr = nullptr;
    cudaGetSymbolAddress(&tm_ptr, g_tmU);
    cudaMemsetAsync(tm_ptr, 0, (size_t)NROWS * NSB * sizeof(unsigned), 0);

    shiftconv_kernel<<<QUEUE * DIM / (256 * 4), 256>>>(fq, out);
    norm_kernel<<<NROWS, 256>>>(p1, p2, out + 2048);
    screen_kernel<<<dim3(64, 8), 256, 131072>>>();
    recheck_kernel<<<NROWS, 256>>>(fq);
    logits_kernel<<<dim3(8, 8, 2), dim3(16, 16)>>>(fq);
    loss_kernel<<<2048, 512>>>(out);
}

// round 17
// speedup vs baseline: 4.6993x; 1.0377x over previous
#include <cuda_runtime.h>
#include <cuda_bf16.h>
#include <stdint.h>

#define BATCH 512
#define DIM   256
#define QUEUE 65536
#define NROWS 1024
#define NSB   1024          // 64-row queue sub-blocks
#define QG    8             // queue tiles (128 rows) per screen CTA
#define SB_MARGIN 0.016f
#define EL_MARGIN 0.012f
#define MAXCAND 256

// ---------------- device scratch (allocations forbidden) ----------------
__device__ __align__(16) float          g_P [NROWS * DIM];   // normalized fp32
__device__ __align__(16) __nv_bfloat16  g_Pb[NROWS * DIM];   // normalized bf16
__device__ __align__(16) __nv_bfloat16  g_Qb[QUEUE * DIM];   // queue bf16
__device__ __align__(16) __nv_bfloat16  g_sim[(size_t)NROWS * QUEUE]; // bf16 sims (128MB)
__device__ unsigned                     g_tmU[NROWS * NSB];  // ordered-float keys of subblock maxima
__device__ unsigned long long           g_best[NROWS];       // packed (key<<32 | ~idx), exact
__device__ __align__(16) float          g_S[2 * BATCH * BATCH];

// ---------------- helpers ----------------
__device__ __forceinline__ unsigned float_key(float v) {
    unsigned u = __float_as_uint(v);
    return (u & 0x80000000u) ? ~u : (u | 0x80000000u);
}
__device__ __forceinline__ float key_float(unsigned k) {
    unsigned u = (k & 0x80000000u) ? (k & 0x7FFFFFFFu) : ~k;
    return __uint_as_float(u);
}
__device__ __forceinline__ uint32_t smem_u32(const void* p) {
    uint32_t a;
    asm("{ .reg .u64 t; cvta.to.shared.u64 t, %1; cvt.u32.u64 %0, t; }" : "=r"(a) : "l"(p));
    return a;
}
__device__ __forceinline__ void cp16(uint32_t dst, const void* src) {
    asm volatile("cp.async.cg.shared.global [%0], [%1], 16;" :: "r"(dst), "l"(src));
}
__device__ __forceinline__ void cp_commit() {
    asm volatile("cp.async.commit_group;" ::: "memory");
}
__device__ __forceinline__ void ldsm_x4(uint32_t& r0, uint32_t& r1, uint32_t& r2, uint32_t& r3,
                                        uint32_t addr) {
    asm volatile("ldmatrix.sync.aligned.m8n8.x4.shared.b16 {%0,%1,%2,%3}, [%4];"
                 : "=r"(r0), "=r"(r1), "=r"(r2), "=r"(r3) : "r"(addr));
}
__device__ __forceinline__ void mma16816(float* c, const uint32_t* a, const uint32_t* b) {
    asm volatile(
        "mma.sync.aligned.m16n8k16.row.col.f32.bf16.bf16.f32 "
        "{%0,%1,%2,%3}, {%4,%5,%6,%7}, {%8,%9}, {%0,%1,%2,%3};"
        : "+f"(c[0]), "+f"(c[1]), "+f"(c[2]), "+f"(c[3])
        : "r"(a[0]), "r"(a[1]), "r"(a[2]), "r"(a[3]), "r"(b[0]), "r"(b[1]));
}

// ---------------- kernel 0: queue shift + bf16 convert (fused) ----------------
__global__ void __launch_bounds__(256) shiftconv_kernel(const float* __restrict__ fq,
                                                        float* __restrict__ out) {
    size_t i = ((size_t)blockIdx.x * 256 + threadIdx.x) * 4;
    float4 v = *(const float4*)(fq + i);
    *(__nv_bfloat162*)(g_Qb + i)     = __floats2bfloat162_rn(v.x, v.y);
    *(__nv_bfloat162*)(g_Qb + i + 2) = __floats2bfloat162_rn(v.z, v.w);
    size_t row = i >> 8;
    if (row < (size_t)(QUEUE - BATCH))
        *(float4*)(out + 2048 + (row + BATCH) * DIM + (i & 255)) = v;
}

// ---------------- kernel 1: L2 normalize ----------------
__global__ void __launch_bounds__(256) norm_kernel(const float* __restrict__ p1,
                                                   const float* __restrict__ p2,
                                                   float* __restrict__ outq) {
    int row = blockIdx.x, t = threadIdx.x;
    const float* src = (row < BATCH) ? (p1 + (size_t)row * DIM)
                                     : (p2 + (size_t)(row - BATCH) * DIM);
    float x = src[t];
    float s = x * x;
    #pragma unroll
    for (int off = 16; off; off >>= 1) s += __shfl_xor_sync(0xFFFFFFFFu, s, off);
    __shared__ float ws[8];
    if ((t & 31) == 0) ws[t >> 5] = s;
    __syncthreads();
    float sum = 0.f;
    #pragma unroll
    for (int i = 0; i < 8; i++) sum += ws[i];
    float sc = rsqrtf(fmaxf(sum, 1e-12f));
    float y = x * sc;
    g_P[row * DIM + t]  = y;
    g_Pb[row * DIM + t] = __float2bfloat16(y);
    if (row < BATCH) outq[(size_t)row * DIM + t] = y;
}

// ---------------- kernel 2: bf16 mma.sync screen (cp.async double-buffered B) ----------------
// grid (64, 8): bx = group of 8 queue tiles (128 rows each), by = 128-row P group.
// smem: A @0 (64KB), B0 @64K, B1 @128K. chunked k-major layout:
//   byte = kc*4096 + row*32 + half*16, XOR'd by ((row&4)<<2).
__global__ void __launch_bounds__(256) screen_kernel() {
    extern __shared__ __align__(16) char smem[];
    const uint32_t sbase = smem_u32(smem);
    const int tid = threadIdx.x;
    const int lane = tid & 31, w = tid >> 5;
    const int wm = w >> 2, wn = w & 3;           // warp 64(M) x 32(N) tile
    const int qg = blockIdx.x, pg = blockIdx.y;
    const uint32_t sB[2] = { sbase + 65536, sbase + 131072 };

    // ---- async load A (P group: 128 rows x 256 bf16) ----
    #pragma unroll
    for (int i = 0; i < 16; i++) {
        int idx = i * 256 + tid;                 // 16B chunk id
        int row = idx >> 5, ch = idx & 31;
        uint32_t off = (uint32_t)((ch >> 1) * 4096 + row * 32 + (ch & 1) * 16);
        off ^= (row & 4) << 2;
        cp16(sbase + off, &g_Pb[(size_t)(pg * 128 + row) * DIM + ch * 8]);
    }
    // ---- async load B tile 0 ----
    #pragma unroll
    for (int i = 0; i < 16; i++) {
        int idx = i * 256 + tid;
        int row = idx >> 5, ch = idx & 31;
        uint32_t off = (uint32_t)((ch >> 1) * 4096 + row * 32 + (ch & 1) * 16);
        off ^= (row & 4) << 2;
        cp16(sB[0] + off, &g_Qb[((size_t)(qg * QG) * 128 + row) * DIM + ch * 8]);
    }
    cp_commit();

    // per-lane ldmatrix offset constants (relative to tile base)
    uint32_t a_addr[4], b_off[2];
    #pragma unroll
    for (int mi = 0; mi < 4; mi++) {
        uint32_t off = (uint32_t)((wm * 64 + mi * 16 + (lane & 15)) * 32 + (lane >> 4) * 16);
        off ^= (lane & 4) << 2;
        a_addr[mi] = sbase + off;
    }
    #pragma unroll
    for (int ni2 = 0; ni2 < 2; ni2++) {
        uint32_t off = (uint32_t)((wn * 32 + ni2 * 16 + (lane & 15)) * 32 + (lane >> 4) * 16);
        off ^= (lane & 4) << 2;
        b_off[ni2] = off;
    }

    for (int t8 = 0; t8 < QG; t8++) {
        const int qt = qg * QG + t8;
        // ---- prefetch next B tile into the other buffer ----
        if (t8 + 1 < QG) {
            #pragma unroll
            for (int i = 0; i < 16; i++) {
                int idx = i * 256 + tid;
                int row = idx >> 5, ch = idx & 31;
                uint32_t off = (uint32_t)((ch >> 1) * 4096 + row * 32 + (ch & 1) * 16);
                off ^= (row & 4) << 2;
                cp16(sB[(t8 + 1) & 1] + off,
                     &g_Qb[((size_t)(qt + 1) * 128 + row) * DIM + ch * 8]);
            }
            cp_commit();
            asm volatile("cp.async.wait_group 1;" ::: "memory");
        } else {
            asm volatile("cp.async.wait_group 0;" ::: "memory");
        }
        __syncthreads();

        const uint32_t bbase = sB[t8 & 1];
        float c[4][4][4];
        #pragma unroll
        for (int mi = 0; mi < 4; mi++)
            #pragma unroll
            for (int ni = 0; ni < 4; ni++)
                #pragma unroll
                for (int e = 0; e < 4; e++) c[mi][ni][e] = 0.f;

        #pragma unroll
        for (int ks = 0; ks < 16; ks++) {
            const uint32_t kb = (uint32_t)(ks * 4096);
            uint32_t a[4][4];
            #pragma unroll
            for (int mi = 0; mi < 4; mi++)
                ldsm_x4(a[mi][0], a[mi][1], a[mi][2], a[mi][3], a_addr[mi] + kb);
            uint32_t b[4][2];
            #pragma unroll
            for (int ni2 = 0; ni2 < 2; ni2++) {
                uint32_t r0, r1, r2, r3;
                ldsm_x4(r0, r1, r2, r3, bbase + b_off[ni2] + kb);
                b[ni2 * 2 + 0][0] = r0; b[ni2 * 2 + 0][1] = r2;
                b[ni2 * 2 + 1][0] = r1; b[ni2 * 2 + 1][1] = r3;
            }
            #pragma unroll
            for (int mi = 0; mi < 4; mi++)
                #pragma unroll
                for (int ni = 0; ni < 4; ni++)
                    mma16816(c[mi][ni], a[mi], b[ni]);
        }

        // ---- epilogue: store bf16 sims + per (row, 64-subblock) max ----
        const int sb = qt * 2 + (wn >> 1);
        #pragma unroll
        for (int mi = 0; mi < 4; mi++) {
            const int rlo = pg * 128 + wm * 64 + mi * 16 + (lane >> 2);
            float mlo = -1e30f, mhi = -1e30f;
            #pragma unroll
            for (int ni = 0; ni < 4; ni++) {
                const int col = qt * 128 + wn * 32 + ni * 8 + (lane & 3) * 2;
                *(__nv_bfloat162*)&g_sim[(size_t)rlo * QUEUE + col] =
                    __floats2bfloat162_rn(c[mi][ni][0], c[mi][ni][1]);
                *(__nv_bfloat162*)&g_sim[(size_t)(rlo + 8) * QUEUE + col] =
                    __floats2bfloat162_rn(c[mi][ni][2], c[mi][ni][3]);
                mlo = fmaxf(mlo, fmaxf(c[mi][ni][0], c[mi][ni][1]));
                mhi = fmaxf(mhi, fmaxf(c[mi][ni][2], c[mi][ni][3]));
            }
            #pragma unroll
            for (int off = 1; off <= 2; off <<= 1) {
                mlo = fmaxf(mlo, __shfl_xor_sync(0xFFFFFFFFu, mlo, off));
                mhi = fmaxf(mhi, __shfl_xor_sync(0xFFFFFFFFu, mhi, off));
            }
            if ((lane & 3) == 0) {
                atomicMax(&g_tmU[(size_t)rlo * NSB + sb], float_key(mlo));
                atomicMax(&g_tmU[(size_t)(rlo + 8) * NSB + sb], float_key(mhi));
            }
        }
        __syncthreads();
    }
}

// ---------------- kernel 3: element-granularity exact recheck ----------------
// one block (256 thr) per P row.
__global__ void __launch_bounds__(256) recheck_kernel(const float* __restrict__ fq) {
    const int row = blockIdx.x, t = threadIdx.x, wid = t >> 5, lane = t & 31;
    __shared__ __align__(16) float Pk[DIM];
    __shared__ unsigned redk[8];
    __shared__ int cand[MAXCAND];
    __shared__ int ccount;
    __shared__ unsigned long long cbest[MAXCAND];

    if (t == 0) ccount = 0;
    Pk[t] = g_P[row * DIM + t];

    unsigned myk[4];
    unsigned mk = 0;
    #pragma unroll
    for (int i = 0; i < 4; i++) {
        myk[i] = g_tmU[(size_t)row * NSB + t + i * 256];
        mk = max(mk, myk[i]);
    }
    #pragma unroll
    for (int off = 16; off; off >>= 1) mk = max(mk, __shfl_xor_sync(0xFFFFFFFFu, mk, off));
    if (lane == 0) redk[wid] = mk;
    __syncthreads();
    unsigned maxk = 0;
    #pragma unroll
    for (int w2 = 0; w2 < 8; w2++) maxk = max(maxk, redk[w2]);
    const float fmaxv  = key_float(maxk);
    const float sb_thr = fmaxv - SB_MARGIN;
    const float el_thr = fmaxv - EL_MARGIN;

    // phase A: candidate discovery from stored bf16 sims
    #pragma unroll
    for (int i = 0; i < 4; i++) {
        int sb = t + i * 256;
        if (key_float(myk[i]) >= sb_thr) {
            const __nv_bfloat162* sp =
                (const __nv_bfloat162*)&g_sim[(size_t)row * QUEUE + sb * 64];
            #pragma unroll 4
            for (int j = 0; j < 32; j++) {
                __nv_bfloat162 v = sp[j];
                float lo = __bfloat162float(v.x);
                float hi = __bfloat162float(v.y);
                if (lo >= el_thr) {
                    int ix = atomicAdd(&ccount, 1);
                    if (ix < MAXCAND) cand[ix] = sb * 64 + j * 2;
                }
                if (hi >= el_thr) {
                    int ix = atomicAdd(&ccount, 1);
                    if (ix < MAXCAND) cand[ix] = sb * 64 + j * 2 + 1;
                }
            }
        }
    }
    __syncthreads();
    const int C = min(ccount, MAXCAND);

    // phase B: exact fp32 dot per candidate, one warp each
    for (int ci = wid; ci < C; ci += 8) {
        unsigned q = (unsigned)cand[ci];
        const float* qr = fq + (size_t)q * DIM;
        float s = 0.f;
        #pragma unroll
        for (int k = 0; k < 8; k++)
            s = fmaf(qr[lane + 32 * k], Pk[lane + 32 * k], s);
        #pragma unroll
        for (int off = 16; off; off >>= 1) s += __shfl_xor_sync(0xFFFFFFFFu, s, off);
        if (lane == 0)
            cbest[ci] = ((unsigned long long)float_key(s) << 32) | (unsigned)(~q);
    }
    __syncthreads();
    if (t == 0) {
        unsigned long long m = 0ULL;
        for (int ci = 0; ci < C; ci++) m = (cbest[ci] > m) ? cbest[ci] : m;
        g_best[row] = m;
    }
}

// ---------------- kernel 4: logits S_z = NN_z . P_other^T / T ----------------
__global__ void __launch_bounds__(256) logits_kernel(const float* __restrict__ fq) {
    __shared__ float As[64][34];
    __shared__ float Bs[64][34];
    const int tx = threadIdx.x, ty = threadIdx.y;
    const int t = ty * 16 + tx;
    const int bx = blockIdx.x, by = blockIdx.y, z = blockIdx.z;
    const int zoff = z ? 0 : BATCH;

    float acc[4][4];
    #pragma unroll
    for (int i = 0; i < 4; i++)
        #pragma unroll
        for (int j = 0; j < 4; j++) acc[i][j] = 0.f;

    for (int kc = 0; kc < DIM; kc += 32) {
        __syncthreads();
        #pragma unroll
        for (int l = 0; l < 2; ++l) {
            int idx = l * 256 + t;
            int row = idx >> 3;
            int k4  = (idx & 7) * 4;
            unsigned q = ~(unsigned)(g_best[z * BATCH + by * 64 + row] & 0xFFFFFFFFu);
            float4 v = *(const float4*)&fq[(size_t)q * DIM + kc + k4];
            As[row][k4 + 0] = v.x; As[row][k4 + 1] = v.y;
            As[row][k4 + 2] = v.z; As[row][k4 + 3] = v.w;
            float4 w = *(const float4*)&g_P[(size_t)(zoff + bx * 64 + row) * DIM + kc + k4];
            Bs[row][k4 + 0] = w.x; Bs[row][k4 + 1] = w.y;
            Bs[row][k4 + 2] = w.z; Bs[row][k4 + 3] = w.w;
        }
        __syncthreads();
        #pragma unroll
        for (int k = 0; k < 32; k++) {
            float a[4], b[4];
            #pragma unroll
            for (int i = 0; i < 4; i++) a[i] = As[ty * 4 + i][k];
            #pragma unroll
            for (int j = 0; j < 4; j++) b[j] = Bs[tx + 16 * j][k];
            #pragma unroll
            for (int i = 0; i < 4; i++)
                #pragma unroll
                for (int j = 0; j < 4; j++) acc[i][j] = fmaf(a[i], b[j], acc[i][j]);
        }
    }
    #pragma unroll
    for (int i = 0; i < 4; i++) {
        int brow = by * 64 + ty * 4 + i;
        #pragma unroll
        for (int j = 0; j < 4; j++) {
            int ccol = bx * 64 + tx + 16 * j;
            g_S[((size_t)z * BATCH + brow) * BATCH + ccol] = acc[i][j] * 10.0f;
        }
    }
}

// ---------------- kernel 5: loss (row / column log-softmax) ----------------
__global__ void __launch_bounds__(512) loss_kernel(float* __restrict__ out) {
    const int r = blockIdx.x, t = threadIdx.x;
    const int g = r >> 9, i = r & 511;
    const int z = g >> 1, colside = g & 1;
    const float* S = g_S + (size_t)z * BATCH * BATCH;
    float v = colside ? S[(size_t)t * BATCH + i] : S[(size_t)i * BATCH + t];
    float diag = S[(size_t)i * BATCH + i];

    __shared__ float red[16];
    float m = v;
    #pragma unroll
    for (int off = 16; off; off >>= 1) m = fmaxf(m, __shfl_xor_sync(0xFFFFFFFFu, m, off));
    if ((t & 31) == 0) red[t >> 5] = m;
    __syncthreads();
    if (t == 0) {
        float mm = red[0];
        #pragma unroll
        for (int w = 1; w < 16; w++) mm = fmaxf(mm, red[w]);
        red[0] = mm;
    }
    __syncthreads();
    m = red[0];
    __syncthreads();

    float e = __expf(v - m);
    #pragma unroll
    for (int off = 16; off; off >>= 1) e += __shfl_xor_sync(0xFFFFFFFFu, e, off);
    if ((t & 31) == 0) red[t >> 5] = e;
    __syncthreads();
    if (t == 0) {
        float sum = 0.f;
        #pragma unroll
        for (int w = 0; w < 16; w++) sum += red[w];
        out[r] = m + logf(sum) - diag;
    }
}

// ---------------- launch ----------------
extern "C" void kernel_launch(void* const* d_in, const int* in_sizes, int n_in,
                              void* d_out, int out_size) {
    const float* p1 = (const float*)d_in[0];
    const float* p2 = (const float*)d_in[1];
    const float* fq = (const float*)d_in[2];
    float* out = (float*)d_out;

    static int init_done = 0;
    if (!init_done) {
        cudaFuncSetAttribute(screen_kernel, cudaFuncAttributeMaxDynamicSharedMemorySize,
                             196608);
        init_done = 1;
    }

    void* tm_ptr = nullptr;
    cudaGetSymbolAddress(&tm_ptr, g_tmU);
    cudaMemsetAsync(tm_ptr, 0, (size_t)NROWS * NSB * sizeof(unsigned), 0);

    shiftconv_kernel<<<QUEUE * DIM / (256 * 4), 256>>>(fq, out);
    norm_kernel<<<NROWS, 256>>>(p1, p2, out + 2048);
    screen_kernel<<<dim3(64, 8), 256, 196608>>>();
    recheck_kernel<<<NROWS, 256>>>(fq);
    logits_kernel<<<dim3(8, 8, 2), dim3(16, 16)>>>(fq);
    loss_kernel<<<2048, 512>>>(out);
}